// round 1
// baseline (speedup 1.0000x reference)
#include <cuda_runtime.h>
#include <math.h>

// Problem constants (fixed by the dataset)
#define T_TOK 4096
#define HID   1024
#define INTER 4096
#define NEXP  8

// GEMM tiling
#define TM 128
#define TN 64
#define TK 32
#define MAX_TILES 72                 // sum_e ceil(c_e/128) <= 64 + 8
#define MAX_SLOTS (MAX_TILES * TM)   // 9216

// ---------------- device scratch (no allocations allowed) ----------------
__device__ int   g_counts[NEXP];
__device__ int   g_cursor[NEXP];
__device__ int   g_poff[NEXP];        // padded (128-aligned) expert row offsets
__device__ int   g_num_tiles;
__device__ int   g_tile_expert[MAX_TILES];
__device__ int   g_slot_token[MAX_SLOTS];
__device__ int   g_top_idx[T_TOK * 2];
__device__ float g_top_w[T_TOK * 2];
__device__ int   g_tok_slot[T_TOK * 2];
__device__ float g_H[(size_t)MAX_SLOTS * INTER];  // gelu(x @ w1^T), tf32-rounded inputs downstream
__device__ float g_Y[(size_t)MAX_SLOTS * HID];    // expert outputs before combine

// ---------------- helpers ----------------
__device__ __forceinline__ float to_tf32(float v) {
    float r;
    asm("cvt.rna.tf32.f32 %0, %1;" : "=f"(r) : "f"(v));
    return r;
}

#define MMA_TF32(c, a, b)                                                        \
    asm volatile(                                                                \
        "mma.sync.aligned.m16n8k8.row.col.f32.tf32.tf32.f32 "                   \
        "{%0,%1,%2,%3}, {%4,%5,%6,%7}, {%8,%9}, {%0,%1,%2,%3};"                 \
        : "+f"(c[0]), "+f"(c[1]), "+f"(c[2]), "+f"(c[3])                         \
        : "r"(a[0]), "r"(a[1]), "r"(a[2]), "r"(a[3]), "r"(b[0]), "r"(b[1]))

// ---------------- stage 0: reset counters ----------------
__global__ void init_kernel() {
    if (threadIdx.x < NEXP) g_counts[threadIdx.x] = 0;
}

// ---------------- stage 1: router ----------------
// One block (256 thr = 8 warps) per token. Warp e computes logit for expert e
// in fp32 (logits are an output). Thread 0 does top-2 + softmax.
__global__ void router_kernel(const float* __restrict__ x,
                              const float* __restrict__ gw,
                              float* __restrict__ logits_out) {
    __shared__ float xs[HID];
    __shared__ float ls[NEXP];
    int t = blockIdx.x;
    const float4* xp = (const float4*)(x + (size_t)t * HID);
    for (int i = threadIdx.x; i < HID / 4; i += blockDim.x)
        ((float4*)xs)[i] = xp[i];
    __syncthreads();

    int w = threadIdx.x >> 5, lane = threadIdx.x & 31;
    if (w < NEXP) {
        const float* g = gw + (size_t)w * HID;
        float s = 0.f;
        for (int i = lane; i < HID; i += 32) s += xs[i] * g[i];
        #pragma unroll
        for (int o = 16; o; o >>= 1) s += __shfl_xor_sync(0xffffffffu, s, o);
        if (lane == 0) { ls[w] = s; logits_out[(size_t)t * NEXP + w] = s; }
    }
    __syncthreads();

    if (threadIdx.x == 0) {
        int i0 = 0; float v0 = ls[0];
        #pragma unroll
        for (int e = 1; e < NEXP; e++) if (ls[e] > v0) { v0 = ls[e]; i0 = e; }
        int i1 = -1; float v1 = -3.4e38f;
        #pragma unroll
        for (int e = 0; e < NEXP; e++) if (e != i0 && ls[e] > v1) { v1 = ls[e]; i1 = e; }
        float w1v = 1.f / (1.f + expf(v0 - v1));   // softmax over {v0, v1}
        float w0v = 1.f - w1v;
        g_top_idx[2 * t] = i0;  g_top_idx[2 * t + 1] = i1;
        g_top_w[2 * t] = w0v;   g_top_w[2 * t + 1] = w1v;
        atomicAdd(&g_counts[i0], 1);
        atomicAdd(&g_counts[i1], 1);
    }
}

// ---------------- stage 2: padded prefix offsets + tile->expert map ----------------
__global__ void offsets_kernel() {
    int pad = 0, nt = 0;
    for (int e = 0; e < NEXP; e++) {
        g_poff[e] = pad;
        g_cursor[e] = 0;
        int c = g_counts[e];
        int tiles = (c + TM - 1) / TM;
        for (int j = 0; j < tiles; j++) g_tile_expert[nt++] = e;
        pad += tiles * TM;
    }
    g_num_tiles = nt;
}

// ---------------- stage 3: scatter tokens into expert-sorted slots ----------------
__global__ void scatter_kernel() {
    int t = blockIdx.x * blockDim.x + threadIdx.x;
    if (t >= T_TOK) return;
    #pragma unroll
    for (int j = 0; j < 2; j++) {
        int e = g_top_idx[2 * t + j];
        int p = atomicAdd(&g_cursor[e], 1);
        int slot = g_poff[e] + p;
        g_slot_token[slot] = t;
        g_tok_slot[2 * t + j] = slot;
    }
}

// ---------------- stage 4/5: grouped GEMM (tf32 mma.sync) ----------------
// FIRST=true : C = gelu( gather(x) @ w1[e]^T ) -> g_H   (K=1024, N=4096)
// FIRST=false: C =        g_H      @ w2[e]^T   -> g_Y   (K=4096, N=1024)
template <bool FIRST>
__global__ void __launch_bounds__(256, 2)
gemm_kernel(const float* __restrict__ X, const float* __restrict__ W) {
    constexpr int KDIM = FIRST ? HID : INTER;
    constexpr int NTOT = FIRST ? INTER : HID;
    const float* Asrc = FIRST ? X : (const float*)g_H;
    float* C = FIRST ? (float*)g_H : (float*)g_Y;

    int mt = blockIdx.y;
    if (mt >= g_num_tiles) return;
    int e = g_tile_expert[mt];
    int nbase = blockIdx.x * TN;
    int row_base = mt * TM;
    const float* B = W + (size_t)e * NTOT * KDIM;

    __shared__ float As[TM][TK + 4];   // stride 36: conflict-free frag reads
    __shared__ float Bs[TN][TK + 4];
    __shared__ int rtok[TM];

    int tid = threadIdx.x;
    {
        int cnt = g_counts[e];
        int poff = g_poff[e];
        for (int r = tid; r < TM; r += 256) {
            int gr = row_base + r;
            int src;
            if (FIRST) {
                bool valid = (gr - poff) < cnt;
                src = valid ? g_slot_token[gr] : 0;   // padded rows read token 0
            } else {
                src = gr;
            }
            rtok[r] = src;
        }
    }
    __syncthreads();

    int wid = tid >> 5, lane = tid & 31;
    int wm = (wid >> 1) * 32, wn = (wid & 1) * 32;
    int qr = lane >> 2, qc = lane & 3;

    float c[2][4][4];
    #pragma unroll
    for (int mi = 0; mi < 2; mi++)
        #pragma unroll
        for (int ni = 0; ni < 4; ni++)
            #pragma unroll
            for (int j = 0; j < 4; j++) c[mi][ni][j] = 0.f;

    float4 rA[4], rB[2];

    auto loadA = [&](int k0) {
        #pragma unroll
        for (int i = 0; i < 4; i++) {
            int flat = tid + i * 256;
            int r = flat >> 3, kq = flat & 7;
            rA[i] = *(const float4*)(Asrc + (size_t)rtok[r] * KDIM + k0 + kq * 4);
        }
    };
    auto loadB = [&](int k0) {
        #pragma unroll
        for (int i = 0; i < 2; i++) {
            int flat = tid + i * 256;
            int r = flat >> 3, kq = flat & 7;
            rB[i] = *(const float4*)(B + (size_t)(nbase + r) * KDIM + k0 + kq * 4);
        }
    };
    auto stage = [&]() {
        #pragma unroll
        for (int i = 0; i < 4; i++) {
            int flat = tid + i * 256;
            int r = flat >> 3, kq = flat & 7;
            As[r][kq * 4 + 0] = to_tf32(rA[i].x);
            As[r][kq * 4 + 1] = to_tf32(rA[i].y);
            As[r][kq * 4 + 2] = to_tf32(rA[i].z);
            As[r][kq * 4 + 3] = to_tf32(rA[i].w);
        }
        #pragma unroll
        for (int i = 0; i < 2; i++) {
            int flat = tid + i * 256;
            int r = flat >> 3, kq = flat & 7;
            Bs[r][kq * 4 + 0] = to_tf32(rB[i].x);
            Bs[r][kq * 4 + 1] = to_tf32(rB[i].y);
            Bs[r][kq * 4 + 2] = to_tf32(rB[i].z);
            Bs[r][kq * 4 + 3] = to_tf32(rB[i].w);
        }
    };

    loadA(0); loadB(0);
    const int NC = KDIM / TK;
    for (int kc = 0; kc < NC; kc++) {
        stage();
        __syncthreads();
        if (kc + 1 < NC) { loadA((kc + 1) * TK); loadB((kc + 1) * TK); }
        #pragma unroll
        for (int kk = 0; kk < TK; kk += 8) {
            unsigned a[2][4], b[4][2];
            #pragma unroll
            for (int mi = 0; mi < 2; mi++) {
                int r0 = wm + mi * 16 + qr;
                a[mi][0] = __float_as_uint(As[r0    ][kk + qc]);
                a[mi][1] = __float_as_uint(As[r0 + 8][kk + qc]);
                a[mi][2] = __float_as_uint(As[r0    ][kk + qc + 4]);
                a[mi][3] = __float_as_uint(As[r0 + 8][kk + qc + 4]);
            }
            #pragma unroll
            for (int ni = 0; ni < 4; ni++) {
                int n0 = wn + ni * 8 + qr;
                b[ni][0] = __float_as_uint(Bs[n0][kk + qc]);
                b[ni][1] = __float_as_uint(Bs[n0][kk + qc + 4]);
            }
            #pragma unroll
            for (int mi = 0; mi < 2; mi++)
                #pragma unroll
                for (int ni = 0; ni < 4; ni++)
                    MMA_TF32(c[mi][ni], a[mi], b[ni]);
        }
        __syncthreads();
    }

    // epilogue
    #pragma unroll
    for (int mi = 0; mi < 2; mi++) {
        #pragma unroll
        for (int ni = 0; ni < 4; ni++) {
            int r0 = row_base + wm + mi * 16 + qr;
            int col = nbase + wn + ni * 8 + 2 * qc;
            float v0 = c[mi][ni][0], v1 = c[mi][ni][1];
            float v2 = c[mi][ni][2], v3 = c[mi][ni][3];
            if (FIRST) {  // exact gelu: x * Phi(x)
                v0 = v0 * normcdff(v0);
                v1 = v1 * normcdff(v1);
                v2 = v2 * normcdff(v2);
                v3 = v3 * normcdff(v3);
            }
            *(float2*)(C + (size_t)r0 * NTOT + col)       = make_float2(v0, v1);
            *(float2*)(C + (size_t)(r0 + 8) * NTOT + col) = make_float2(v2, v3);
        }
    }
}

// ---------------- stage 6: weighted combine (top-2) ----------------
__global__ void combine_kernel(float* __restrict__ out) {
    int t = blockIdx.x;
    int s0 = g_tok_slot[2 * t], s1 = g_tok_slot[2 * t + 1];
    float w0 = g_top_w[2 * t], w1 = g_top_w[2 * t + 1];
    const float4* y0 = (const float4*)(g_Y + (size_t)s0 * HID);
    const float4* y1 = (const float4*)(g_Y + (size_t)s1 * HID);
    float4* o = (float4*)(out + (size_t)t * HID);
    int i = threadIdx.x;   // 256 threads, HID/4 = 256 float4 per token
    float4 a = y0[i], b = y1[i];
    o[i] = make_float4(w0 * a.x + w1 * b.x, w0 * a.y + w1 * b.y,
                       w0 * a.z + w1 * b.z, w0 * a.w + w1 * b.w);
}

// ---------------- launch ----------------
extern "C" void kernel_launch(void* const* d_in, const int* in_sizes, int n_in,
                              void* d_out, int out_size) {
    const float* x  = (const float*)d_in[0];   // hidden_states [2,2048,1024]
    const float* gw = (const float*)d_in[1];   // gate_w [8,1024]
    const float* w1 = (const float*)d_in[2];   // w1 [8,4096,1024]
    const float* w2 = (const float*)d_in[3];   // w2 [8,1024,4096]
    float* out = (float*)d_out;                         // [4096,1024]
    float* logits = out + (size_t)T_TOK * HID;          // [4096,8]

    init_kernel<<<1, 32>>>();
    router_kernel<<<T_TOK, 256>>>(x, gw, logits);
    offsets_kernel<<<1, 1>>>();
    scatter_kernel<<<16, 256>>>();
    gemm_kernel<true ><<<dim3(INTER / TN, MAX_TILES), 256>>>(x, w1);
    gemm_kernel<false><<<dim3(HID / TN, MAX_TILES), 256>>>(x, w2);
    combine_kernel<<<T_TOK, 256>>>(out);
}

// round 5
// speedup vs baseline: 2.5841x; 2.5841x over previous
#include <cuda_runtime.h>
#include <cuda_fp16.h>
#include <cstdint>
#include <math.h>

// ---------------- problem constants ----------------
#define T_TOK 4096
#define HID   1024
#define INTER 4096
#define NEXP  8

// ---------------- GEMM tiling ----------------
#define TM 128           // CTA M
#define TNB 128          // CTA N
#define CK 64            // K halves per chunk (128B rows)
#define STAGES 3
#define MAX_TILES 72
#define MAX_SLOTS (MAX_TILES * TM)

// smem: stage s at s*32768 (A 16KB + B 16KB); rtok after stages
#define STAGE_BYTES 32768
#define SMEM_RTOK   (STAGES * STAGE_BYTES)
#define SMEM_TOTAL  (SMEM_RTOK + 512)

// ---------------- device scratch (16B-aligned) ----------------
__device__ __align__(16) int    g_counts[NEXP];
__device__ __align__(16) int    g_cursor[NEXP];
__device__ __align__(16) int    g_poff[NEXP];
__device__ __align__(16) int    g_num_tiles_pad[4];
__device__ __align__(16) int    g_tile_expert[MAX_TILES];
__device__ __align__(16) int    g_slot_token[MAX_SLOTS];
__device__ __align__(16) int    g_top_idx[T_TOK * 2];
__device__ __align__(16) float  g_top_w[T_TOK * 2];
__device__ __align__(16) int    g_tok_slot[T_TOK * 2];
__device__ __align__(16) __half g_xh[(size_t)T_TOK * HID];          // fp16 activations
__device__ __align__(16) __half g_w1h[(size_t)NEXP * INTER * HID];  // fp16 w1
__device__ __align__(16) __half g_w2h[(size_t)NEXP * HID * INTER];  // fp16 w2
__device__ __align__(16) __half g_Hh[(size_t)MAX_SLOTS * INTER];    // fp16 gelu(x@w1^T)
__device__ __align__(16) float  g_Y[(size_t)MAX_SLOTS * HID];

#define g_num_tiles (g_num_tiles_pad[0])

// ---------------- PTX helpers ----------------
__device__ __forceinline__ uint32_t smem_to_u32(const void* p) {
    uint32_t a;
    asm("{ .reg .u64 t; cvta.to.shared.u64 t, %1; cvt.u32.u64 %0, t; }" : "=r"(a) : "l"(p));
    return a;
}
#define CP_ASYNC16(dst, src) \
    asm volatile("cp.async.cg.shared.global [%0], [%1], 16;" :: "r"(dst), "l"(src))
#define CP_COMMIT() asm volatile("cp.async.commit_group;" ::: "memory")
#define CP_WAIT(n)  asm volatile("cp.async.wait_group %0;" :: "n"(n) : "memory")

__device__ __forceinline__ void ldsm_x4(uint32_t& r0, uint32_t& r1, uint32_t& r2, uint32_t& r3,
                                        uint32_t addr) {
    asm volatile("ldmatrix.sync.aligned.m8n8.x4.shared.b16 {%0,%1,%2,%3}, [%4];"
                 : "=r"(r0), "=r"(r1), "=r"(r2), "=r"(r3) : "r"(addr));
}
#define MMA_F16(c, a0, a1, a2, a3, b0, b1)                                      \
    asm volatile("mma.sync.aligned.m16n8k16.row.col.f32.f16.f16.f32 "           \
                 "{%0,%1,%2,%3}, {%4,%5,%6,%7}, {%8,%9}, {%0,%1,%2,%3};"        \
                 : "+f"(c[0]), "+f"(c[1]), "+f"(c[2]), "+f"(c[3])               \
                 : "r"(a0), "r"(a1), "r"(a2), "r"(a3), "r"(b0), "r"(b1))

#define SWZ(off) ((off) ^ (((off) >> 3) & 0x70))

// ---------------- stage 0: reset ----------------
__global__ void init_kernel() {
    if (threadIdx.x < NEXP) g_counts[threadIdx.x] = 0;
}

// ---------------- weight fp32->fp16 convert ----------------
__global__ void convert_w_kernel(const float* __restrict__ src, __half* __restrict__ dst) {
    int i = blockIdx.x * blockDim.x + threadIdx.x;   // float4 index
    float4 v = ((const float4*)src)[i];
    __half2 lo = __floats2half2_rn(v.x, v.y);
    __half2 hi = __floats2half2_rn(v.z, v.w);
    ((__half2*)dst)[2 * i]     = lo;
    ((__half2*)dst)[2 * i + 1] = hi;
}

// ---------------- stage 1: router (+ fp16 activation write) ----------------
__global__ void router_kernel(const float* __restrict__ x,
                              const float* __restrict__ gw,
                              float* __restrict__ logits_out) {
    __shared__ float xs[HID];
    __shared__ float ls[NEXP];
    int t = blockIdx.x;
    const float4* xp = (const float4*)(x + (size_t)t * HID);
    __half2* xh = (__half2*)(g_xh + (size_t)t * HID);
    for (int i = threadIdx.x; i < HID / 4; i += blockDim.x) {
        float4 v = xp[i];
        ((float4*)xs)[i] = v;
        xh[2 * i]     = __floats2half2_rn(v.x, v.y);
        xh[2 * i + 1] = __floats2half2_rn(v.z, v.w);
    }
    __syncthreads();

    int w = threadIdx.x >> 5, lane = threadIdx.x & 31;
    if (w < NEXP) {
        const float* g = gw + (size_t)w * HID;
        float s = 0.f;
        for (int i = lane; i < HID; i += 32) s += xs[i] * g[i];
        #pragma unroll
        for (int o = 16; o; o >>= 1) s += __shfl_xor_sync(0xffffffffu, s, o);
        if (lane == 0) { ls[w] = s; logits_out[(size_t)t * NEXP + w] = s; }
    }
    __syncthreads();

    if (threadIdx.x == 0) {
        int i0 = 0; float v0 = ls[0];
        #pragma unroll
        for (int e = 1; e < NEXP; e++) if (ls[e] > v0) { v0 = ls[e]; i0 = e; }
        int i1 = -1; float v1 = -3.4e38f;
        #pragma unroll
        for (int e = 0; e < NEXP; e++) if (e != i0 && ls[e] > v1) { v1 = ls[e]; i1 = e; }
        float w1v = 1.f / (1.f + expf(v0 - v1));
        float w0v = 1.f - w1v;
        g_top_idx[2 * t] = i0;  g_top_idx[2 * t + 1] = i1;
        g_top_w[2 * t] = w0v;   g_top_w[2 * t + 1] = w1v;
        atomicAdd(&g_counts[i0], 1);
        atomicAdd(&g_counts[i1], 1);
    }
}

// ---------------- stage 2: offsets ----------------
__global__ void offsets_kernel() {
    int pad = 0, nt = 0;
    for (int e = 0; e < NEXP; e++) {
        g_poff[e] = pad;
        g_cursor[e] = 0;
        int c = g_counts[e];
        int tiles = (c + TM - 1) / TM;
        for (int j = 0; j < tiles; j++) g_tile_expert[nt++] = e;
        pad += tiles * TM;
    }
    g_num_tiles = nt;
}

// ---------------- stage 3: scatter ----------------
__global__ void scatter_kernel() {
    int t = blockIdx.x * blockDim.x + threadIdx.x;
    if (t >= T_TOK) return;
    #pragma unroll
    for (int j = 0; j < 2; j++) {
        int e = g_top_idx[2 * t + j];
        int p = atomicAdd(&g_cursor[e], 1);
        int slot = g_poff[e] + p;
        g_slot_token[slot] = t;
        g_tok_slot[2 * t + j] = slot;
    }
}

// ---------------- stage 4/5: fp16 grouped GEMM (cp.async + ldmatrix + mma) ----------------
// FIRST=true : g_Hh = half( gelu( gather(g_xh) @ w1h[e]^T ) )   K=1024, Ntot=4096
// FIRST=false: g_Y  = g_Hh @ w2h[e]^T                           K=4096, Ntot=1024
template <bool FIRST>
__global__ void __launch_bounds__(256, 2)
gemm_f16(const __half* __restrict__ Asrc, const __half* __restrict__ W) {
    constexpr int KDIM = FIRST ? HID : INTER;
    constexpr int NTOT = FIRST ? INTER : HID;
    constexpr int NC = KDIM / CK;

    int mt = blockIdx.y;
    if (mt >= g_num_tiles) return;

    extern __shared__ char smem[];
    uint32_t sb = smem_to_u32(smem);
    int tid = threadIdx.x;
    int lane = tid & 31, wid = tid >> 5;

    int e = g_tile_expert[mt];
    int row_base = mt * TM;
    const __half* B = W + (size_t)e * NTOT * KDIM + (size_t)(blockIdx.x * TNB) * KDIM;

    int* rtok = (int*)(smem + SMEM_RTOK);
    if (tid < TM) {
        int gr = row_base + tid;
        int src;
        if (FIRST) {
            int cnt = g_counts[e], poff = g_poff[e];
            src = (gr - poff) < cnt ? g_slot_token[gr] : 0;
        } else {
            src = gr;
        }
        rtok[tid] = src;
    }
    __syncthreads();

    // per-thread cp.async assignments: 4 x 16B for A tile, 4 x 16B for B tile
    // (128 rows x 8 16B-chunks = 1024 chunks per operand; 256 thr x 4 = 1024)
    const __half* asrc[4]; const __half* bsrc[4];
    uint32_t adst[4], bdst[4];
    #pragma unroll
    for (int i = 0; i < 4; i++) {
        int f = tid + i * 256;
        int row = f >> 3, c = f & 7;
        asrc[i] = Asrc + (size_t)rtok[row] * KDIM + c * 8;
        adst[i] = sb + SWZ(row * 128 + c * 16);
        bsrc[i] = B + (size_t)row * KDIM + c * 8;
        bdst[i] = sb + 16384u + SWZ(row * 128 + c * 16);
    }

    auto issue = [&](int kc, int s) {
        uint32_t off = (uint32_t)s * STAGE_BYTES;
        size_t koff = (size_t)kc * CK;
        #pragma unroll
        for (int i = 0; i < 4; i++) {
            CP_ASYNC16(adst[i] + off, (const void*)(asrc[i] + koff));
            CP_ASYNC16(bdst[i] + off, (const void*)(bsrc[i] + koff));
        }
    };

    // warp tile 64(M) x 32(N); warp grid 2 x 4
    int wm = (wid & 1) * 64;
    int wn = (wid >> 1) * 32;
    int qr = lane >> 2, qc = lane & 3;

    // ldmatrix address row-bytes (pre-swizzle)
    uint32_t arow[4], brow[2];
    #pragma unroll
    for (int mi = 0; mi < 4; mi++)
        arow[mi] = (uint32_t)(wm + mi * 16 + (lane & 15)) * 128u + ((lane >> 4) << 4);
    #pragma unroll
    for (int nb = 0; nb < 2; nb++)
        brow[nb] = (uint32_t)(wn + nb * 16 + ((lane >> 4) & 1) * 8 + (lane & 7)) * 128u
                   + (((lane >> 3) & 1) << 4);

    float c[4][4][4];
    #pragma unroll
    for (int mi = 0; mi < 4; mi++)
        #pragma unroll
        for (int ni = 0; ni < 4; ni++)
            #pragma unroll
            for (int j = 0; j < 4; j++) c[mi][ni][j] = 0.f;

    issue(0, 0); CP_COMMIT();
    if (NC > 1) issue(1, 1);
    CP_COMMIT();

    for (int kc = 0; kc < NC; kc++) {
        CP_WAIT(1);
        __syncthreads();
        int nk = kc + STAGES - 1;
        if (nk < NC) issue(nk, nk % STAGES);
        CP_COMMIT();

        uint32_t soff = (uint32_t)(kc % STAGES) * STAGE_BYTES;
        uint32_t abase = sb + soff;
        uint32_t bbase = sb + soff + 16384u;
        #pragma unroll
        for (int ks = 0; ks < 4; ks++) {
            uint32_t a[4][4], b[2][4];
            #pragma unroll
            for (int mi = 0; mi < 4; mi++)
                ldsm_x4(a[mi][0], a[mi][1], a[mi][2], a[mi][3],
                        abase + SWZ(arow[mi] + ks * 32));
            #pragma unroll
            for (int nb = 0; nb < 2; nb++)
                ldsm_x4(b[nb][0], b[nb][1], b[nb][2], b[nb][3],
                        bbase + SWZ(brow[nb] + ks * 32));
            #pragma unroll
            for (int mi = 0; mi < 4; mi++) {
                #pragma unroll
                for (int nb = 0; nb < 2; nb++) {
                    MMA_F16(c[mi][nb * 2 + 0], a[mi][0], a[mi][1], a[mi][2], a[mi][3],
                            b[nb][0], b[nb][1]);
                    MMA_F16(c[mi][nb * 2 + 1], a[mi][0], a[mi][1], a[mi][2], a[mi][3],
                            b[nb][2], b[nb][3]);
                }
            }
        }
    }

    // ---------------- epilogue ----------------
    #pragma unroll
    for (int mi = 0; mi < 4; mi++) {
        #pragma unroll
        for (int ni = 0; ni < 4; ni++) {
            int r0 = row_base + wm + mi * 16 + qr;
            int col = blockIdx.x * TNB + wn + ni * 8 + 2 * qc;
            float v0 = c[mi][ni][0], v1 = c[mi][ni][1];
            float v2 = c[mi][ni][2], v3 = c[mi][ni][3];
            if (FIRST) {
                v0 *= normcdff(v0); v1 *= normcdff(v1);
                v2 *= normcdff(v2); v3 *= normcdff(v3);
                __half2* d0 = (__half2*)(g_Hh + (size_t)r0 * NTOT + col);
                __half2* d1 = (__half2*)(g_Hh + (size_t)(r0 + 8) * NTOT + col);
                *d0 = __floats2half2_rn(v0, v1);
                *d1 = __floats2half2_rn(v2, v3);
            } else {
                *(float2*)(g_Y + (size_t)r0 * NTOT + col)       = make_float2(v0, v1);
                *(float2*)(g_Y + (size_t)(r0 + 8) * NTOT + col) = make_float2(v2, v3);
            }
        }
    }
}

// ---------------- stage 6: combine ----------------
__global__ void combine_kernel(float* __restrict__ out) {
    int t = blockIdx.x;
    int s0 = g_tok_slot[2 * t], s1 = g_tok_slot[2 * t + 1];
    float w0 = g_top_w[2 * t], w1 = g_top_w[2 * t + 1];
    const float4* y0 = (const float4*)(g_Y + (size_t)s0 * HID);
    const float4* y1 = (const float4*)(g_Y + (size_t)s1 * HID);
    float4* o = (float4*)(out + (size_t)t * HID);
    int i = threadIdx.x;
    float4 a = y0[i], b = y1[i];
    o[i] = make_float4(w0 * a.x + w1 * b.x, w0 * a.y + w1 * b.y,
                       w0 * a.z + w1 * b.z, w0 * a.w + w1 * b.w);
}

// ---------------- launch ----------------
extern "C" void kernel_launch(void* const* d_in, const int* in_sizes, int n_in,
                              void* d_out, int out_size) {
    const float* x  = (const float*)d_in[0];
    const float* gw = (const float*)d_in[1];
    const float* w1 = (const float*)d_in[2];
    const float* w2 = (const float*)d_in[3];
    float* out = (float*)d_out;
    float* logits = out + (size_t)T_TOK * HID;

    cudaFuncSetAttribute(gemm_f16<true>,  cudaFuncAttributeMaxDynamicSharedMemorySize, SMEM_TOTAL);
    cudaFuncSetAttribute(gemm_f16<false>, cudaFuncAttributeMaxDynamicSharedMemorySize, SMEM_TOTAL);

    __half* w1h; cudaGetSymbolAddress((void**)&w1h, g_w1h);
    __half* w2h; cudaGetSymbolAddress((void**)&w2h, g_w2h);
    __half* xh;  cudaGetSymbolAddress((void**)&xh,  g_xh);
    __half* Hh;  cudaGetSymbolAddress((void**)&Hh,  g_Hh);

    init_kernel<<<1, 32>>>();
    router_kernel<<<T_TOK, 256>>>(x, gw, logits);
    offsets_kernel<<<1, 1>>>();
    scatter_kernel<<<16, 256>>>();
    const int W_ELEMS4 = NEXP * INTER * HID / 4;
    convert_w_kernel<<<W_ELEMS4 / 256, 256>>>(w1, w1h);
    convert_w_kernel<<<W_ELEMS4 / 256, 256>>>(w2, w2h);
    gemm_f16<true ><<<dim3(INTER / TNB, MAX_TILES), 256, SMEM_TOTAL>>>(xh, w1h);
    gemm_f16<false><<<dim3(HID / TNB, MAX_TILES), 256, SMEM_TOTAL>>>(Hh, w2h);
    combine_kernel<<<T_TOK, 256>>>(out);
}